// round 14
// baseline (speedup 1.0000x reference)
#include <cuda_runtime.h>
#include <cuda_bf16.h>
#include <cstdint>

#define N_NODES 50000
#define N_EDGES 800000
#define N_GRAPHS 1000
#define X_DIM 128
#define HIDDEN 256
#define N_LAYERS 3
#define N_CLASS 10
#define HN (N_NODES * HIDDEN)

typedef __nv_bfloat16 bf16;

// ---------------- device scratch ----------------
__device__ float g_h0[HN];                           // f32 activations (final layer only)
__device__ bf16  g_h0b[HN], g_h1b[HN];               // bf16 activations (ping/pong)
__device__ bf16  g_aggb[HN];                         // bf16 aggregated messages
__device__ bf16  g_xb[N_NODES * X_DIM];
__device__ bf16  g_wtehi[HIDDEN * X_DIM], g_wtelo[HIDDEN * X_DIM];   // W_enc^T [n][k] hi/lo
__device__ bf16  g_wtlhi[N_LAYERS * HIDDEN * HIDDEN], g_wtllo[N_LAYERS * HIDDEN * HIDDEN];
__device__ bf16  g_wtrhi[N_LAYERS * HIDDEN * HIDDEN], g_wtrlo[N_LAYERS * HIDDEN * HIDDEN];
__device__ int   g_deg[N_NODES];
__device__ int   g_off[N_NODES];
__device__ int   g_cur[N_NODES];
__device__ float g_invdeg[N_NODES];
__device__ int   g_src_sorted[N_EDGES];
__device__ float g_att_sorted[N_EDGES];
__device__ int   g_gstart[N_GRAPHS];
__device__ int   g_gend[N_GRAPHS];

// ---------------- helpers ----------------
__device__ __forceinline__ uint32_t smem_u32(const void* p) {
    uint32_t a;
    asm("{ .reg .u64 t; cvta.to.shared.u64 t, %1; cvt.u32.u64 %0, t; }" : "=r"(a) : "l"(p));
    return a;
}
__device__ __forceinline__ void split_bf16(float v, bf16& hi, bf16& lo) {
    hi = __float2bfloat16(v);
    lo = __float2bfloat16(v - __bfloat162float(hi));
}

__global__ void zero_int_kernel(int* p, int n) {
    int i = blockIdx.x * blockDim.x + threadIdx.x;
    if (i < n) p[i] = 0;
}
__global__ void degree_kernel(const int* __restrict__ dst) {
    int e = blockIdx.x * blockDim.x + threadIdx.x;
    if (e < N_EDGES) atomicAdd(&g_deg[dst[e]], 1);
}
__global__ void scan_kernel() {
    const int NT = 1024;
    const int CHUNK = (N_NODES + NT - 1) / NT;
    __shared__ int sums[NT];
    int t = threadIdx.x;
    int begin = t * CHUNK;
    int end = begin + CHUNK; if (end > N_NODES) end = N_NODES;
    int s = 0;
    for (int i = begin; i < end; i++) s += g_deg[i];
    sums[t] = s;
    __syncthreads();
    for (int off = 1; off < NT; off <<= 1) {
        int v = (t >= off) ? sums[t - off] : 0;
        __syncthreads();
        sums[t] += v;
        __syncthreads();
    }
    int run = sums[t] - s;
    for (int i = begin; i < end; i++) {
        g_off[i] = run;
        g_cur[i] = run;
        int d = g_deg[i];
        g_invdeg[i] = 1.0f / (float)(d > 1 ? d : 1);
        run += d;
    }
}
__global__ void fill_csr_kernel(const int* __restrict__ src, const int* __restrict__ dst,
                                const float* __restrict__ atten) {
    int e = blockIdx.x * blockDim.x + threadIdx.x;
    if (e < N_EDGES) {
        int d = dst[e];
        int pos = atomicAdd(&g_cur[d], 1);
        g_src_sorted[pos] = src[e];
        g_att_sorted[pos] = atten[e];
    }
}
__global__ void gbounds_init_kernel() {
    int g = blockIdx.x * blockDim.x + threadIdx.x;
    if (g < N_GRAPHS) { g_gstart[g] = N_NODES; g_gend[g] = 0; }
}
__global__ void gbounds_kernel(const int* __restrict__ batch) {
    int i = blockIdx.x * blockDim.x + threadIdx.x;
    if (i < N_NODES) {
        int b = batch[i];
        atomicMin(&g_gstart[b], i);
        atomicMax(&g_gend[b], i + 1);
    }
}
__global__ void split_x_kernel(const float* __restrict__ x) {
    int i = blockIdx.x * blockDim.x + threadIdx.x;
    if (i < N_NODES * X_DIM) g_xb[i] = __float2bfloat16(x[i]);
}
// transpose + split weights: src [L][K][N] -> dst [L][N][K] bf16 hi/lo
__global__ void wsplit_kernel(const float* __restrict__ W, bf16* __restrict__ hi,
                              bf16* __restrict__ lo, int K, int N, int L) {
    int idx = blockIdx.x * blockDim.x + threadIdx.x;
    int total = L * K * N;
    if (idx >= total) return;
    int l = idx / (K * N);
    int r = idx - l * K * N;
    int k = r / N;
    int n = r - k * N;
    bf16 h, lw;
    split_bf16(W[idx], h, lw);
    int d = (l * N + n) * K + k;
    hi[d] = h;
    lo[d] = lw;
}

// aggregate from bf16 h: 1 warp per node, lane covers 8 channels (uint4), 4x MLP unroll
__global__ void aggregate_kernel(const bf16* __restrict__ hb) {
    int node = blockIdx.x * 8 + (threadIdx.x >> 5);
    int lane = threadIdx.x & 31;
    if (node >= N_NODES) return;
    int start = g_off[node];
    int d = g_deg[node];
    const int* __restrict__ sp = g_src_sorted + start;
    const float* __restrict__ ap = g_att_sorted + start;
    float acc[8];
#pragma unroll
    for (int j = 0; j < 8; j++) acc[j] = 0.f;

    auto accum = [&](float a, uint4 v) {
        const __nv_bfloat162* p2 = reinterpret_cast<const __nv_bfloat162*>(&v);
#pragma unroll
        for (int j = 0; j < 4; j++) {
            float2 f = __bfloat1622float2(p2[j]);
            acc[2 * j + 0] += a * f.x;
            acc[2 * j + 1] += a * f.y;
        }
    };

    int e = 0;
    for (; e + 4 <= d; e += 4) {
        int s0 = __ldg(sp + e + 0), s1 = __ldg(sp + e + 1);
        int s2 = __ldg(sp + e + 2), s3 = __ldg(sp + e + 3);
        float a0 = __ldg(ap + e + 0), a1 = __ldg(ap + e + 1);
        float a2 = __ldg(ap + e + 2), a3 = __ldg(ap + e + 3);
        uint4 v0 = *reinterpret_cast<const uint4*>(hb + (size_t)s0 * HIDDEN + lane * 8);
        uint4 v1 = *reinterpret_cast<const uint4*>(hb + (size_t)s1 * HIDDEN + lane * 8);
        uint4 v2 = *reinterpret_cast<const uint4*>(hb + (size_t)s2 * HIDDEN + lane * 8);
        uint4 v3 = *reinterpret_cast<const uint4*>(hb + (size_t)s3 * HIDDEN + lane * 8);
        accum(a0, v0); accum(a1, v1); accum(a2, v2); accum(a3, v3);
    }
    for (; e < d; e++) {
        int s = __ldg(sp + e);
        float a = __ldg(ap + e);
        uint4 v = *reinterpret_cast<const uint4*>(hb + (size_t)s * HIDDEN + lane * 8);
        accum(a, v);
    }

    float id = g_invdeg[node];
    bf16 h8[8];
#pragma unroll
    for (int j = 0; j < 8; j++) h8[j] = __float2bfloat16(acc[j] * id);
    *reinterpret_cast<uint4*>(g_aggb + (size_t)node * HIDDEN + lane * 8) =
        *reinterpret_cast<uint4*>(h8);
}

// ---------------- HMMA bf16 fused multi-source GEMM ----------------
// BM=128, BN=128, 256 threads (8 warps 4x2), NSTAGE-deep cp.async pipeline.
// Per K-chunk stage: NA activation tiles + 2*NA weight tiles (hi, lo per source).
// All terms computed per chunk; A fragments reused across hi/lo weights.
struct TermsF {
    const bf16* a[2];    // activation sources
    const bf16* b[4];    // b[2s+0]=W_hi, b[2s+1]=W_lo for source s
};

#define ROWS_S 40                       // 80B row stride (5x16B), ldmatrix conflict-free
#define TILE_B (128 * ROWS_S * 2)       // 10240 B per tile

__device__ __forceinline__ void ldm_x4(uint32_t* r, uint32_t addr) {
    asm volatile("ldmatrix.sync.aligned.m8n8.x4.shared.b16 {%0,%1,%2,%3}, [%4];"
                 : "=r"(r[0]), "=r"(r[1]), "=r"(r[2]), "=r"(r[3]) : "r"(addr));
}
__device__ __forceinline__ void mma_bf16(float* d, const uint32_t* a, uint32_t b0, uint32_t b1) {
    asm volatile(
        "mma.sync.aligned.m16n8k16.row.col.f32.bf16.bf16.f32 "
        "{%0,%1,%2,%3}, {%4,%5,%6,%7}, {%8,%9}, {%0,%1,%2,%3};"
        : "+f"(d[0]), "+f"(d[1]), "+f"(d[2]), "+f"(d[3])
        : "r"(a[0]), "r"(a[1]), "r"(a[2]), "r"(a[3]), "r"(b0), "r"(b1));
}
__device__ __forceinline__ void cp_async16(uint32_t dst, const void* src, int srcsize) {
    asm volatile("cp.async.cg.shared.global [%0], [%1], 16, %2;"
                 :: "r"(dst), "l"(src), "r"(srcsize) : "memory");
}
#define CP_COMMIT() asm volatile("cp.async.commit_group;" ::: "memory")
#define CP_WAIT(n)  asm volatile("cp.async.wait_group %0;" :: "n"(n) : "memory")

template <int K, int NA, int NSTAGE, bool RELU, bool WRITEBF16, bool WRITEF32>
__global__ __launch_bounds__(256) void mma_gemm(
    TermsF terms, const float* __restrict__ bias,
    float* __restrict__ C, bf16* __restrict__ Cb, int M)
{
    extern __shared__ char dsmem[];
    const uint32_t sbase = smem_u32(dsmem);

    const int tid = threadIdx.x;
    const int lane = tid & 31, wid = tid >> 5;
    const int warp_m = wid & 3, warp_n = wid >> 2;   // 4 x 2 warps
    const int m0 = blockIdx.y * 128, n0 = blockIdx.x * 128;

    constexpr int NTILE = 3 * NA;          // tiles per stage
    constexpr int STAGE_B = NTILE * TILE_B;
    constexpr int NCH = K / 32;

    float d[2][8][4];
#pragma unroll
    for (int i = 0; i < 2; i++)
#pragma unroll
        for (int j = 0; j < 8; j++)
#pragma unroll
            for (int q = 0; q < 4; q++) d[i][j][q] = 0.f;

    // chunk loader: NA A-tiles then 2*NA B-tiles, each 128 rows x 32 cols bf16
    auto load_chunk = [&](int buf, int c) {
        const int k0 = c * 32;
        const uint32_t sb = sbase + buf * STAGE_B;
        // A tiles (guard M)
#pragma unroll
        for (int s = 0; s < NA; s++) {
            const bf16* Ap = terms.a[s];
#pragma unroll
            for (int h = 0; h < 2; h++) {
                int u = tid + h * 256;
                int row = u >> 2, seg = u & 3;
                int grow = m0 + row;
                int valid = grow < M;
                const bf16* ga = Ap + (size_t)(valid ? grow : 0) * K + k0 + seg * 8;
                cp_async16(sb + s * TILE_B + (row * ROWS_S + seg * 8) * 2, ga, valid ? 16 : 0);
            }
        }
        // B tiles (weights: 256 rows, always valid)
#pragma unroll
        for (int w = 0; w < 2 * NA; w++) {
            const bf16* Bp = terms.b[w];
#pragma unroll
            for (int h = 0; h < 2; h++) {
                int u = tid + h * 256;
                int row = u >> 2, seg = u & 3;
                const bf16* gb = Bp + (size_t)(n0 + row) * K + k0 + seg * 8;
                cp_async16(sb + (NA + w) * TILE_B + (row * ROWS_S + seg * 8) * 2, gb, 16);
            }
        }
        CP_COMMIT();
    };

#pragma unroll
    for (int p = 0; p < NSTAGE - 1; p++) load_chunk(p, p);

    const uint32_t aBase = ((warp_m * 32 + (lane & 15)) * ROWS_S + (lane >> 4) * 8) * 2;
    const uint32_t bBase = ((warp_n * 64 + (lane & 15)) * ROWS_S + (lane >> 4) * 8) * 2;

    for (int c = 0; c < NCH; c++) {
        CP_WAIT(NSTAGE - 2);
        __syncthreads();
        if (c + NSTAGE - 1 < NCH) load_chunk((c + NSTAGE - 1) % NSTAGE, c + NSTAGE - 1);
        else CP_COMMIT();

        const int buf = c % NSTAGE;
        const uint32_t stg = sbase + buf * STAGE_B;
#pragma unroll
        for (int ks = 0; ks < 2; ks++) {
#pragma unroll
            for (int s = 0; s < NA; s++) {
                uint32_t afr[2][4];
#pragma unroll
                for (int mi = 0; mi < 2; mi++)
                    ldm_x4(afr[mi], stg + s * TILE_B + aBase + ks * 32 + mi * 16 * ROWS_S * 2);
#pragma unroll
                for (int w = 0; w < 2; w++) {
                    const uint32_t bb = stg + (NA + 2 * s + w) * TILE_B + bBase + ks * 32;
#pragma unroll
                    for (int p = 0; p < 4; p++) {
                        uint32_t br[4];
                        ldm_x4(br, bb + p * 16 * ROWS_S * 2);
#pragma unroll
                        for (int mi = 0; mi < 2; mi++) {
                            mma_bf16(d[mi][2 * p + 0], afr[mi], br[0], br[2]);
                            mma_bf16(d[mi][2 * p + 1], afr[mi], br[1], br[3]);
                        }
                    }
                }
            }
        }
    }

    // epilogue
#pragma unroll
    for (int mi = 0; mi < 2; mi++) {
        const int rb = m0 + warp_m * 32 + mi * 16 + (lane >> 2);
#pragma unroll
        for (int j = 0; j < 8; j++) {
            const int cb = n0 + warp_n * 64 + j * 8 + (lane & 3) * 2;
            const float bx = __ldg(bias + cb), by = __ldg(bias + cb + 1);
#pragma unroll
            for (int half = 0; half < 2; half++) {
                const int r = rb + half * 8;
                if (r >= M) continue;
                float vx = d[mi][j][half * 2 + 0] + bx;
                float vy = d[mi][j][half * 2 + 1] + by;
                if (RELU) {
                    vx = vx > 0.f ? vx : 0.f;
                    vy = vy > 0.f ? vy : 0.f;
                }
                if (WRITEF32)
                    *reinterpret_cast<float2*>(C + (size_t)r * HIDDEN + cb) = make_float2(vx, vy);
                if (WRITEBF16) {
                    bf16 h2[2] = {__float2bfloat16(vx), __float2bfloat16(vy)};
                    *reinterpret_cast<uint32_t*>(Cb + (size_t)r * HIDDEN + cb) =
                        *reinterpret_cast<uint32_t*>(h2);
                }
            }
        }
    }
}

// fused pool + head: block per graph (batch sorted -> contiguous node ranges)
__global__ void pool_head_kernel(const float* __restrict__ h, const float* __restrict__ W,
                                 const float* __restrict__ b, float* __restrict__ out) {
    __shared__ float sh[HIDDEN];
    int g = blockIdx.x;
    int s = g_gstart[g], e = g_gend[g];
    int c = threadIdx.x;
    float acc = 0.f;
    for (int n = s; n < e; n++) acc += h[(size_t)n * HIDDEN + c];
    sh[c] = acc;
    __syncthreads();
    if (c < N_CLASS) {
        float sum = __ldg(b + c);
#pragma unroll 8
        for (int k = 0; k < HIDDEN; k++) sum += sh[k] * __ldg(W + k * N_CLASS + c);
        out[(size_t)g * N_CLASS + c] = sum;
    }
}

extern "C" void kernel_launch(void* const* d_in, const int* in_sizes, int n_in,
                              void* d_out, int out_size) {
    const float* x        = (const float*)d_in[0];
    const int*   edge_idx = (const int*)d_in[1];
    const int*   batch    = (const int*)d_in[2];
    const float* edge_att = (const float*)d_in[3];
    const float* W_enc    = (const float*)d_in[4];
    const float* b_enc    = (const float*)d_in[5];
    const float* W_l      = (const float*)d_in[6];
    const float* b_l      = (const float*)d_in[7];
    const float* W_r      = (const float*)d_in[8];
    const float* W_out    = (const float*)d_in[9];
    const float* b_out    = (const float*)d_in[10];
    float* out = (float*)d_out;

    const int* src = edge_idx;
    const int* dst = edge_idx + N_EDGES;

    float* h0;
    bf16 *h0b, *h1b, *aggb, *xb;
    bf16 *wtehi, *wtelo, *wtlhi, *wtllo, *wtrhi, *wtrlo;
    int* deg;
    cudaGetSymbolAddress((void**)&h0, g_h0);
    cudaGetSymbolAddress((void**)&h0b, g_h0b);
    cudaGetSymbolAddress((void**)&h1b, g_h1b);
    cudaGetSymbolAddress((void**)&aggb, g_aggb);
    cudaGetSymbolAddress((void**)&xb, g_xb);
    cudaGetSymbolAddress((void**)&wtehi, g_wtehi);
    cudaGetSymbolAddress((void**)&wtelo, g_wtelo);
    cudaGetSymbolAddress((void**)&wtlhi, g_wtlhi);
    cudaGetSymbolAddress((void**)&wtllo, g_wtllo);
    cudaGetSymbolAddress((void**)&wtrhi, g_wtrhi);
    cudaGetSymbolAddress((void**)&wtrlo, g_wtrlo);
    cudaGetSymbolAddress((void**)&deg, g_deg);

    // smem: encoder NA=1, 3 tiles x 4 stages = 122880; layers NA=2, 6 tiles x 3 stages = 184320
    const int SMEM_ENC = 4 * 3 * TILE_B;
    const int SMEM_LAY = 3 * 6 * TILE_B;
    cudaFuncSetAttribute(mma_gemm<X_DIM, 1, 4, false, true, false>,
                         cudaFuncAttributeMaxDynamicSharedMemorySize, SMEM_ENC);
    cudaFuncSetAttribute(mma_gemm<HIDDEN, 2, 3, true, true, false>,
                         cudaFuncAttributeMaxDynamicSharedMemorySize, SMEM_LAY);
    cudaFuncSetAttribute(mma_gemm<HIDDEN, 2, 3, true, false, true>,
                         cudaFuncAttributeMaxDynamicSharedMemorySize, SMEM_LAY);

    // 1) CSR + graph bounds
    zero_int_kernel<<<(N_NODES + 255) / 256, 256>>>(deg, N_NODES);
    degree_kernel<<<(N_EDGES + 255) / 256, 256>>>(dst);
    scan_kernel<<<1, 1024>>>();
    fill_csr_kernel<<<(N_EDGES + 255) / 256, 256>>>(src, dst, edge_att);
    gbounds_init_kernel<<<(N_GRAPHS + 255) / 256, 256>>>();
    gbounds_kernel<<<(N_NODES + 255) / 256, 256>>>(batch);

    // 2) operand prep (activations bf16; weights transposed + split hi/lo)
    split_x_kernel<<<(N_NODES * X_DIM + 255) / 256, 256>>>(x);
    wsplit_kernel<<<(X_DIM * HIDDEN + 255) / 256, 256>>>(W_enc, wtehi, wtelo, X_DIM, HIDDEN, 1);
    wsplit_kernel<<<(N_LAYERS * HIDDEN * HIDDEN + 255) / 256, 256>>>(W_l, wtlhi, wtllo, HIDDEN, HIDDEN, N_LAYERS);
    wsplit_kernel<<<(N_LAYERS * HIDDEN * HIDDEN + 255) / 256, 256>>>(W_r, wtrhi, wtrlo, HIDDEN, HIDDEN, N_LAYERS);

    const int MT = (N_NODES + 127) / 128;
    dim3 grid(2, MT);

    // 3) encoder: h0b = bf16(x @ (We_hi + We_lo) + b_enc)
    {
        TermsF t;
        t.a[0] = xb;     t.a[1] = xb;
        t.b[0] = wtehi;  t.b[1] = wtelo;
        t.b[2] = wtehi;  t.b[3] = wtelo;   // unused (NA=1)
        mma_gemm<X_DIM, 1, 4, false, true, false><<<grid, 256, SMEM_ENC>>>(
            t, b_enc, nullptr, h0b, N_NODES);
    }

    // 4) layers: h' = relu(agg @ (Wl_hi+Wl_lo) + h @ (Wr_hi+Wr_lo) + b)
    bf16 *hcb = h0b, *hnb = h1b;
    for (int l = 0; l < N_LAYERS; l++) {
        aggregate_kernel<<<(N_NODES + 7) / 8, 256>>>(hcb);
        TermsF t;
        t.a[0] = aggb;  t.a[1] = hcb;
        t.b[0] = wtlhi + (size_t)l * HIDDEN * HIDDEN;
        t.b[1] = wtllo + (size_t)l * HIDDEN * HIDDEN;
        t.b[2] = wtrhi + (size_t)l * HIDDEN * HIDDEN;
        t.b[3] = wtrlo + (size_t)l * HIDDEN * HIDDEN;
        const float* bb = b_l + (size_t)l * HIDDEN;
        if (l < N_LAYERS - 1) {
            mma_gemm<HIDDEN, 2, 3, true, true, false><<<grid, 256, SMEM_LAY>>>(
                t, bb, nullptr, hnb, N_NODES);
        } else {
            mma_gemm<HIDDEN, 2, 3, true, false, true><<<grid, 256, SMEM_LAY>>>(
                t, bb, h0, nullptr, N_NODES);
        }
        bf16* tb = hcb; hcb = hnb; hnb = tb;
    }

    // 5) fused pool + head
    pool_head_kernel<<<N_GRAPHS, HIDDEN>>>(h0, W_out, b_out, out);
}

// round 15
// speedup vs baseline: 1.3885x; 1.3885x over previous
#include <cuda_runtime.h>
#include <cuda_fp16.h>
#include <cstdint>

#define N_NODES 50000
#define N_EDGES 800000
#define N_GRAPHS 1000
#define X_DIM 128
#define HIDDEN 256
#define N_LAYERS 3
#define N_CLASS 10
#define HN (N_NODES * HIDDEN)

typedef __half fp16;

// ---------------- device scratch ----------------
__device__ float g_h0[HN];                           // f32 activations (final layer only)
__device__ fp16  g_h0b[HN], g_h1b[HN];               // fp16 activations (ping/pong)
__device__ fp16  g_aggb[HN];                         // fp16 aggregated messages
__device__ fp16  g_xb[N_NODES * X_DIM];
__device__ fp16  g_wte[HIDDEN * X_DIM];              // W_enc^T [n][k]
__device__ fp16  g_wtl[N_LAYERS * HIDDEN * HIDDEN];
__device__ fp16  g_wtr[N_LAYERS * HIDDEN * HIDDEN];
__device__ int   g_deg[N_NODES];
__device__ int   g_off[N_NODES];
__device__ int   g_cur[N_NODES];
__device__ float g_invdeg[N_NODES];
__device__ int   g_src_sorted[N_EDGES];
__device__ float g_att_sorted[N_EDGES];
__device__ int   g_gstart[N_GRAPHS];
__device__ int   g_gend[N_GRAPHS];

// ---------------- helpers ----------------
__device__ __forceinline__ uint32_t smem_u32(const void* p) {
    uint32_t a;
    asm("{ .reg .u64 t; cvta.to.shared.u64 t, %1; cvt.u32.u64 %0, t; }" : "=r"(a) : "l"(p));
    return a;
}

__global__ void zero_int_kernel(int* p, int n) {
    int i = blockIdx.x * blockDim.x + threadIdx.x;
    if (i < n) p[i] = 0;
}
__global__ void degree_kernel(const int* __restrict__ dst) {
    int e = blockIdx.x * blockDim.x + threadIdx.x;
    if (e < N_EDGES) atomicAdd(&g_deg[dst[e]], 1);
}
__global__ void scan_kernel() {
    const int NT = 1024;
    const int CHUNK = (N_NODES + NT - 1) / NT;
    __shared__ int sums[NT];
    int t = threadIdx.x;
    int begin = t * CHUNK;
    int end = begin + CHUNK; if (end > N_NODES) end = N_NODES;
    int s = 0;
    for (int i = begin; i < end; i++) s += g_deg[i];
    sums[t] = s;
    __syncthreads();
    for (int off = 1; off < NT; off <<= 1) {
        int v = (t >= off) ? sums[t - off] : 0;
        __syncthreads();
        sums[t] += v;
        __syncthreads();
    }
    int run = sums[t] - s;
    for (int i = begin; i < end; i++) {
        g_off[i] = run;
        g_cur[i] = run;
        int d = g_deg[i];
        g_invdeg[i] = 1.0f / (float)(d > 1 ? d : 1);
        run += d;
    }
}
__global__ void fill_csr_kernel(const int* __restrict__ src, const int* __restrict__ dst,
                                const float* __restrict__ atten) {
    int e = blockIdx.x * blockDim.x + threadIdx.x;
    if (e < N_EDGES) {
        int d = dst[e];
        int pos = atomicAdd(&g_cur[d], 1);
        g_src_sorted[pos] = src[e];
        g_att_sorted[pos] = atten[e];
    }
}
__global__ void gbounds_init_kernel() {
    int g = blockIdx.x * blockDim.x + threadIdx.x;
    if (g < N_GRAPHS) { g_gstart[g] = N_NODES; g_gend[g] = 0; }
}
__global__ void gbounds_kernel(const int* __restrict__ batch) {
    int i = blockIdx.x * blockDim.x + threadIdx.x;
    if (i < N_NODES) {
        int b = batch[i];
        atomicMin(&g_gstart[b], i);
        atomicMax(&g_gend[b], i + 1);
    }
}
__global__ void split_x_kernel(const float* __restrict__ x) {
    int i = blockIdx.x * blockDim.x + threadIdx.x;
    if (i < N_NODES * X_DIM) g_xb[i] = __float2half(x[i]);
}
// transpose + convert weights: src [L][K][N] -> dst [L][N][K] fp16
__global__ void wsplit_kernel(const float* __restrict__ W, fp16* __restrict__ o,
                              int K, int N, int L) {
    int idx = blockIdx.x * blockDim.x + threadIdx.x;
    int total = L * K * N;
    if (idx >= total) return;
    int l = idx / (K * N);
    int r = idx - l * K * N;
    int k = r / N;
    int n = r - k * N;
    o[(l * N + n) * K + k] = __float2half(W[idx]);
}

// aggregate from fp16 h: 1 warp per node, lane covers 8 channels (uint4), 4x MLP unroll
__global__ void aggregate_kernel(const fp16* __restrict__ hb) {
    int node = blockIdx.x * 8 + (threadIdx.x >> 5);
    int lane = threadIdx.x & 31;
    if (node >= N_NODES) return;
    int start = g_off[node];
    int d = g_deg[node];
    const int* __restrict__ sp = g_src_sorted + start;
    const float* __restrict__ ap = g_att_sorted + start;
    float acc[8];
#pragma unroll
    for (int j = 0; j < 8; j++) acc[j] = 0.f;

    auto accum = [&](float a, uint4 v) {
        const __half2* p2 = reinterpret_cast<const __half2*>(&v);
#pragma unroll
        for (int j = 0; j < 4; j++) {
            float2 f = __half22float2(p2[j]);
            acc[2 * j + 0] += a * f.x;
            acc[2 * j + 1] += a * f.y;
        }
    };

    int e = 0;
    for (; e + 4 <= d; e += 4) {
        int s0 = __ldg(sp + e + 0), s1 = __ldg(sp + e + 1);
        int s2 = __ldg(sp + e + 2), s3 = __ldg(sp + e + 3);
        float a0 = __ldg(ap + e + 0), a1 = __ldg(ap + e + 1);
        float a2 = __ldg(ap + e + 2), a3 = __ldg(ap + e + 3);
        uint4 v0 = *reinterpret_cast<const uint4*>(hb + (size_t)s0 * HIDDEN + lane * 8);
        uint4 v1 = *reinterpret_cast<const uint4*>(hb + (size_t)s1 * HIDDEN + lane * 8);
        uint4 v2 = *reinterpret_cast<const uint4*>(hb + (size_t)s2 * HIDDEN + lane * 8);
        uint4 v3 = *reinterpret_cast<const uint4*>(hb + (size_t)s3 * HIDDEN + lane * 8);
        accum(a0, v0); accum(a1, v1); accum(a2, v2); accum(a3, v3);
    }
    for (; e < d; e++) {
        int s = __ldg(sp + e);
        float a = __ldg(ap + e);
        uint4 v = *reinterpret_cast<const uint4*>(hb + (size_t)s * HIDDEN + lane * 8);
        accum(a, v);
    }

    float id = g_invdeg[node];
    fp16 h8[8];
#pragma unroll
    for (int j = 0; j < 8; j++) h8[j] = __float2half(acc[j] * id);
    *reinterpret_cast<uint4*>(g_aggb + (size_t)node * HIDDEN + lane * 8) =
        *reinterpret_cast<uint4*>(h8);
}

// ---------------- HMMA fp16 GEMM (plain, 1-2 terms), R8-proven shape ----------------
// BM=128, BN=128, 256 threads (8 warps 4x2), 4-stage cp.async pipeline.
struct Terms2 {
    const fp16* a[2];
    const fp16* b[2];
};

#define ROWS_S 40                       // 80B row stride (5x16B), ldmatrix conflict-free
#define OPER_B (128 * ROWS_S * 2)       // 10240 B per operand per stage
#define STAGE_B (2 * OPER_B)            // 20480 B per stage
#define NSTAGE 4
#define GEMM_SMEM (NSTAGE * STAGE_B)    // 81920 B

__device__ __forceinline__ void ldm_x4(uint32_t* r, uint32_t addr) {
    asm volatile("ldmatrix.sync.aligned.m8n8.x4.shared.b16 {%0,%1,%2,%3}, [%4];"
                 : "=r"(r[0]), "=r"(r[1]), "=r"(r[2]), "=r"(r[3]) : "r"(addr));
}
__device__ __forceinline__ void mma_fp16(float* d, const uint32_t* a, uint32_t b0, uint32_t b1) {
    asm volatile(
        "mma.sync.aligned.m16n8k16.row.col.f32.f16.f16.f32 "
        "{%0,%1,%2,%3}, {%4,%5,%6,%7}, {%8,%9}, {%0,%1,%2,%3};"
        : "+f"(d[0]), "+f"(d[1]), "+f"(d[2]), "+f"(d[3])
        : "r"(a[0]), "r"(a[1]), "r"(a[2]), "r"(a[3]), "r"(b0), "r"(b1));
}
__device__ __forceinline__ void cp_async16(uint32_t dst, const void* src, int srcsize) {
    asm volatile("cp.async.cg.shared.global [%0], [%1], 16, %2;"
                 :: "r"(dst), "l"(src), "r"(srcsize) : "memory");
}
#define CP_COMMIT() asm volatile("cp.async.commit_group;" ::: "memory")
#define CP_WAIT(n)  asm volatile("cp.async.wait_group %0;" :: "n"(n) : "memory")

template <int K, int NTERMS, bool RELU, bool WRITEFP16, bool WRITEF32>
__global__ __launch_bounds__(256, 1) void mma_gemm(
    Terms2 terms, const float* __restrict__ bias,
    float* __restrict__ C, fp16* __restrict__ Cb, int M)
{
    extern __shared__ char dsmem[];
    const uint32_t sbase = smem_u32(dsmem);

    const int tid = threadIdx.x;
    const int lane = tid & 31, wid = tid >> 5;
    const int warp_m = wid & 3, warp_n = wid >> 2;   // 4 x 2 warps
    const int m0 = blockIdx.y * 128, n0 = blockIdx.x * 128;

    constexpr int CPT = K / 32;
    constexpr int NCH = NTERMS * CPT;

    float d[2][8][4];
#pragma unroll
    for (int i = 0; i < 2; i++)
#pragma unroll
        for (int j = 0; j < 8; j++)
#pragma unroll
            for (int q = 0; q < 4; q++) d[i][j][q] = 0.f;

    auto load_chunk = [&](int buf, int c) {
        const int term = c / CPT;
        const int k0 = (c - term * CPT) * 32;
        const fp16* Ap = terms.a[term];
        const fp16* Bp = terms.b[term];
        const uint32_t sb = sbase + buf * STAGE_B;
#pragma unroll
        for (int h = 0; h < 2; h++) {
            int u = tid + h * 256;
            int row = u >> 2, seg = u & 3;
            int grow = m0 + row;
            int valid = grow < M;
            const fp16* ga = Ap + (size_t)(valid ? grow : 0) * K + k0 + seg * 8;
            cp_async16(sb + (row * ROWS_S + seg * 8) * 2, ga, valid ? 16 : 0);
            const fp16* gb = Bp + (size_t)(n0 + row) * K + k0 + seg * 8;
            cp_async16(sb + OPER_B + (row * ROWS_S + seg * 8) * 2, gb, 16);
        }
        CP_COMMIT();
    };

    load_chunk(0, 0);
    load_chunk(1, 1);
    load_chunk(2, 2);

    const uint32_t aBase = ((warp_m * 32 + (lane & 15)) * ROWS_S + (lane >> 4) * 8) * 2;
    const uint32_t bBase = ((warp_n * 64 + (lane & 15)) * ROWS_S + (lane >> 4) * 8) * 2;

    for (int c = 0; c < NCH; c++) {
        CP_WAIT(2);
        __syncthreads();
        if (c + 3 < NCH) load_chunk((c + 3) & 3, c + 3);
        else CP_COMMIT();

        const int buf = c & 3;
        const uint32_t aB = sbase + buf * STAGE_B + aBase;
        const uint32_t bB = sbase + buf * STAGE_B + OPER_B + bBase;
#pragma unroll
        for (int ks = 0; ks < 2; ks++) {
            uint32_t afr[2][4];
#pragma unroll
            for (int mi = 0; mi < 2; mi++)
                ldm_x4(afr[mi], aB + ks * 32 + mi * 16 * ROWS_S * 2);
#pragma unroll
            for (int p = 0; p < 4; p++) {
                uint32_t br[4];
                ldm_x4(br, bB + ks * 32 + p * 16 * ROWS_S * 2);
#pragma unroll
                for (int mi = 0; mi < 2; mi++) {
                    mma_fp16(d[mi][2 * p + 0], afr[mi], br[0], br[2]);
                    mma_fp16(d[mi][2 * p + 1], afr[mi], br[1], br[3]);
                }
            }
        }
    }

    // epilogue
#pragma unroll
    for (int mi = 0; mi < 2; mi++) {
        const int rb = m0 + warp_m * 32 + mi * 16 + (lane >> 2);
#pragma unroll
        for (int j = 0; j < 8; j++) {
            const int cb = n0 + warp_n * 64 + j * 8 + (lane & 3) * 2;
            const float bx = __ldg(bias + cb), by = __ldg(bias + cb + 1);
#pragma unroll
            for (int half = 0; half < 2; half++) {
                const int r = rb + half * 8;
                if (r >= M) continue;
                float vx = d[mi][j][half * 2 + 0] + bx;
                float vy = d[mi][j][half * 2 + 1] + by;
                if (RELU) {
                    vx = vx > 0.f ? vx : 0.f;
                    vy = vy > 0.f ? vy : 0.f;
                }
                if (WRITEF32)
                    *reinterpret_cast<float2*>(C + (size_t)r * HIDDEN + cb) = make_float2(vx, vy);
                if (WRITEFP16) {
                    fp16 h2[2] = {__float2half(vx), __float2half(vy)};
                    *reinterpret_cast<uint32_t*>(Cb + (size_t)r * HIDDEN + cb) =
                        *reinterpret_cast<uint32_t*>(h2);
                }
            }
        }
    }
}

// fused pool + head: block per graph (batch sorted -> contiguous node ranges)
__global__ void pool_head_kernel(const float* __restrict__ h, const float* __restrict__ W,
                                 const float* __restrict__ b, float* __restrict__ out) {
    __shared__ float sh[HIDDEN];
    int g = blockIdx.x;
    int s = g_gstart[g], e = g_gend[g];
    int c = threadIdx.x;
    float acc = 0.f;
    for (int n = s; n < e; n++) acc += h[(size_t)n * HIDDEN + c];
    sh[c] = acc;
    __syncthreads();
    if (c < N_CLASS) {
        float sum = __ldg(b + c);
#pragma unroll 8
        for (int k = 0; k < HIDDEN; k++) sum += sh[k] * __ldg(W + k * N_CLASS + c);
        out[(size_t)g * N_CLASS + c] = sum;
    }
}

extern "C" void kernel_launch(void* const* d_in, const int* in_sizes, int n_in,
                              void* d_out, int out_size) {
    const float* x        = (const float*)d_in[0];
    const int*   edge_idx = (const int*)d_in[1];
    const int*   batch    = (const int*)d_in[2];
    const float* edge_att = (const float*)d_in[3];
    const float* W_enc    = (const float*)d_in[4];
    const float* b_enc    = (const float*)d_in[5];
    const float* W_l      = (const float*)d_in[6];
    const float* b_l      = (const float*)d_in[7];
    const float* W_r      = (const float*)d_in[8];
    const float* W_out    = (const float*)d_in[9];
    const float* b_out    = (const float*)d_in[10];
    float* out = (float*)d_out;

    const int* src = edge_idx;
    const int* dst = edge_idx + N_EDGES;

    float* h0;
    fp16 *h0b, *h1b, *aggb, *xb, *wte, *wtl, *wtr;
    int* deg;
    cudaGetSymbolAddress((void**)&h0, g_h0);
    cudaGetSymbolAddress((void**)&h0b, g_h0b);
    cudaGetSymbolAddress((void**)&h1b, g_h1b);
    cudaGetSymbolAddress((void**)&aggb, g_aggb);
    cudaGetSymbolAddress((void**)&xb, g_xb);
    cudaGetSymbolAddress((void**)&wte, g_wte);
    cudaGetSymbolAddress((void**)&wtl, g_wtl);
    cudaGetSymbolAddress((void**)&wtr, g_wtr);
    cudaGetSymbolAddress((void**)&deg, g_deg);

    cudaFuncSetAttribute(mma_gemm<X_DIM, 1, false, true, false>,
                         cudaFuncAttributeMaxDynamicSharedMemorySize, GEMM_SMEM);
    cudaFuncSetAttribute(mma_gemm<HIDDEN, 2, true, true, false>,
                         cudaFuncAttributeMaxDynamicSharedMemorySize, GEMM_SMEM);
    cudaFuncSetAttribute(mma_gemm<HIDDEN, 2, true, false, true>,
                         cudaFuncAttributeMaxDynamicSharedMemorySize, GEMM_SMEM);

    // 1) CSR + graph bounds
    zero_int_kernel<<<(N_NODES + 255) / 256, 256>>>(deg, N_NODES);
    degree_kernel<<<(N_EDGES + 255) / 256, 256>>>(dst);
    scan_kernel<<<1, 1024>>>();
    fill_csr_kernel<<<(N_EDGES + 255) / 256, 256>>>(src, dst, edge_att);
    gbounds_init_kernel<<<(N_GRAPHS + 255) / 256, 256>>>();
    gbounds_kernel<<<(N_NODES + 255) / 256, 256>>>(batch);

    // 2) operand prep (fp16 convert; weights transposed to [n][k])
    split_x_kernel<<<(N_NODES * X_DIM + 255) / 256, 256>>>(x);
    wsplit_kernel<<<(X_DIM * HIDDEN + 255) / 256, 256>>>(W_enc, wte, X_DIM, HIDDEN, 1);
    wsplit_kernel<<<(N_LAYERS * HIDDEN * HIDDEN + 255) / 256, 256>>>(W_l, wtl, HIDDEN, HIDDEN, N_LAYERS);
    wsplit_kernel<<<(N_LAYERS * HIDDEN * HIDDEN + 255) / 256, 256>>>(W_r, wtr, HIDDEN, HIDDEN, N_LAYERS);

    const int MT = (N_NODES + 127) / 128;
    dim3 grid(2, MT);

    // 3) encoder: h0b = fp16(x @ W_enc + b_enc)
    {
        Terms2 t;
        t.a[0] = xb; t.b[0] = wte;
        t.a[1] = xb; t.b[1] = wte;   // unused (NTERMS=1)
        mma_gemm<X_DIM, 1, false, true, false><<<grid, 256, GEMM_SMEM>>>(
            t, b_enc, nullptr, h0b, N_NODES);
    }

    // 4) layers
    fp16 *hcb = h0b, *hnb = h1b;
    for (int l = 0; l < N_LAYERS; l++) {
        aggregate_kernel<<<(N_NODES + 7) / 8, 256>>>(hcb);
        Terms2 t;
        t.a[0] = aggb; t.b[0] = wtl + (size_t)l * HIDDEN * HIDDEN;
        t.a[1] = hcb;  t.b[1] = wtr + (size_t)l * HIDDEN * HIDDEN;
        const float* bb = b_l + (size_t)l * HIDDEN;
        if (l < N_LAYERS - 1) {
            mma_gemm<HIDDEN, 2, true, true, false><<<grid, 256, GEMM_SMEM>>>(
                t, bb, nullptr, hnb, N_NODES);
        } else {
            mma_gemm<HIDDEN, 2, true, false, true><<<grid, 256, GEMM_SMEM>>>(
                t, bb, h0, nullptr, N_NODES);
        }
        fp16* tb = hcb; hcb = hnb; hnb = tb;
    }

    // 5) fused pool + head
    pool_head_kernel<<<N_GRAPHS, HIDDEN>>>(h0, W_out, b_out, out);
}